// round 10
// baseline (speedup 1.0000x reference)
#include <cuda_runtime.h>
#include <cuda_fp16.h>
#include <cuda_bf16.h>

// Synapse_66400194396810: out[m,n] = tanh( w2 . tanh( w1 @ (A[m,n], pre[n], post[m]) + b1 ) + b2 )
// M = N = 4096, Nh = 8.
// R10 (= R9 resubmit; R9 hit a broker infra failure, no data).
// MUFU-floor model: all variants R3-R8 cost 72 MUFU-units/elem -> ~39.6us kernel floor,
// measured 6x within +-1us. Single launch: per-block cooperative weight staging removes
// the pack_weights graph node (~3.4us of bench-vs-kernel gap).

#define NH 8
#define COLS 4096

__device__ __forceinline__ float htanh(float x) {
    float y;
    asm("tanh.approx.f32 %0, %1;" : "=f"(y) : "f"(x));
    return y;
}
__device__ __forceinline__ __half2 htanh2(__half2 x) {
    unsigned yi;
    asm("tanh.approx.f16x2 %0, %1;" : "=r"(yi) : "r"(*(unsigned*)&x));
    return *(__half2*)&yi;
}

__global__ void __launch_bounds__(256) synapse_kernel(
    const float* __restrict__ A,
    const float* __restrict__ pre,
    const float* __restrict__ post,
    const float* __restrict__ w1,
    const float* __restrict__ b1,
    const float* __restrict__ w2,
    const float* __restrict__ b2,
    float* __restrict__ out)
{
    // Per-block weight staging: [0..7]=w10, [8..15]=w11, [16..23]=w12, [24..31]=b1,
    // [32..39]=w2, [40]=b2 (each entry = half2 broadcast).
    __shared__ unsigned sW[48];

    const int tid = threadIdx.x;
    const int row = blockIdx.x;
    const long long base = (long long)row * COLS;

    if (tid < NH) {
        const int h = tid;
        __half2 v;
        v = __half2half2(__float2half_rn(w1[h * 3 + 0])); sW[h]      = *(unsigned*)&v;
        v = __half2half2(__float2half_rn(w1[h * 3 + 1])); sW[8 + h]  = *(unsigned*)&v;
        v = __half2half2(__float2half_rn(w1[h * 3 + 2])); sW[16 + h] = *(unsigned*)&v;
        v = __half2half2(__float2half_rn(b1[h]));         sW[24 + h] = *(unsigned*)&v;
        v = __half2half2(__float2half_rn(w2[h]));         sW[32 + h] = *(unsigned*)&v;
        if (h == 0) {
            v = __half2half2(__float2half_rn(b2[0]));     sW[40]     = *(unsigned*)&v;
        }
    }

    // Weight-independent loads issued before the barrier (overlap staging latency).
    const int n0 = tid * 4;
    const float4 a4_0 = *reinterpret_cast<const float4*>(A + base + n0);
    const float4 p4_0 = *reinterpret_cast<const float4*>(pre + n0);
    const __half2 pm2 = __float2half2_rn(post[row]);

    __syncthreads();

    // Weights -> registers (broadcast LDS, conflict-free).
    __half2 W0[NH], W1h[NH], W2h[NH], CH[NH];
#pragma unroll
    for (int h = 0; h < NH; h++) {
        unsigned u0 = sW[h], u1 = sW[8 + h], u2 = sW[16 + h], ub = sW[24 + h], uo = sW[32 + h];
        W0[h]  = *(__half2*)&u0;
        W1h[h] = *(__half2*)&u1;
        W2h[h] = *(__half2*)&uo;
        CH[h]  = __hfma2(*(__half2*)&u2, pm2, *(__half2*)&ub);
    }
    unsigned ubias = sW[40];
    const __half2 bias2 = *(__half2*)&ubias;

    // 16 elems/thread: 4 coalesced float4 chunks across the row.
#pragma unroll
    for (int j = 0; j < 4; j++) {
        const int n = (j * 256 + tid) * 4;
        const float4 a4 = (j == 0) ? a4_0 : *reinterpret_cast<const float4*>(A + base + n);
        const float4 p4 = (j == 0) ? p4_0 : *reinterpret_cast<const float4*>(pre + n);

        const __half2 a2lo = __floats2half2_rn(a4.x, a4.y);
        const __half2 a2hi = __floats2half2_rn(a4.z, a4.w);
        const __half2 p2lo = __floats2half2_rn(p4.x, p4.y);
        const __half2 p2hi = __floats2half2_rn(p4.z, p4.w);

        __half2 acc_lo = bias2;
        __half2 acc_hi = bias2;
#pragma unroll
        for (int h = 0; h < NH; h++) {
            __half2 zlo = __hfma2(W0[h], a2lo, __hfma2(W1h[h], p2lo, CH[h]));
            __half2 zhi = __hfma2(W0[h], a2hi, __hfma2(W1h[h], p2hi, CH[h]));
            acc_lo = __hfma2(W2h[h], htanh2(zlo), acc_lo);
            acc_hi = __hfma2(W2h[h], htanh2(zhi), acc_hi);
        }
        const float2 flo = __half22float2(acc_lo);
        const float2 fhi = __half22float2(acc_hi);
        float4 o;
        o.x = htanh(flo.x);   // final tanh in fp32 (accuracy headroom)
        o.y = htanh(flo.y);
        o.z = htanh(fhi.x);
        o.w = htanh(fhi.y);
        *reinterpret_cast<float4*>(out + base + n) = o;
    }
}

extern "C" void kernel_launch(void* const* d_in, const int* in_sizes, int n_in,
                              void* d_out, int out_size) {
    const float* A    = (const float*)d_in[0];
    const float* pre  = (const float*)d_in[1];
    const float* post = (const float*)d_in[2];
    const float* w1   = (const float*)d_in[3];
    const float* b1   = (const float*)d_in[4];
    const float* w2   = (const float*)d_in[5];
    const float* b2   = (const float*)d_in[6];
    float* out = (float*)d_out;

    const int M = out_size / COLS;   // 4096 rows, one block per row
    synapse_kernel<<<M, 256>>>(A, pre, post, w1, b1, w2, b2, out);
}